// round 2
// baseline (speedup 1.0000x reference)
#include <cuda_runtime.h>
#include <cstdint>

#define Bz 8
#define Sq 1024
#define Ed 768
#define Hh 12
#define Dd 64
#define N3 2304
#define TOPK 409
#define QT 16
#define KT 64
#define KVP 68   // 64 + 4 pad (stride/4 odd -> limits LDS.128 conflicts to 4-way)

// ---- scratch (allocation-free rule: __device__ globals) ----
__device__ float g_Q[Bz*Hh*Sq*Dd];   // [b,h,s,d]
__device__ float g_K[Bz*Hh*Sq*Dd];
__device__ float g_V[Bz*Hh*Sq*Dd];
__device__ float g_AO[Bz*Sq*Ed];     // attention out, [b,s,h,d] flattened = [8192, 768]

// ============================================================
// GEMM 1: qkv = hidden @ W_qkv + b_qkv, scattered to Q/K/V
// M=8192, N=2304, K=768.  128x128x16 tile, 256 thr, 8x8/thread
// ============================================================
__global__ __launch_bounds__(256) void qkv_gemm(const float* __restrict__ A,
                                                const float* __restrict__ W,
                                                const float* __restrict__ bias) {
    __shared__ float As[16][128];
    __shared__ float Bs[16][128];
    const int t  = threadIdx.x;
    const int tx = t & 15, ty = t >> 4;
    const int m0 = blockIdx.y * 128, n0 = blockIdx.x * 128;
    const int arow = t >> 2, acol = (t & 3) << 2;
    const int brow = t >> 5, bcol = (t & 31) << 2;

    float acc[8][8];
    #pragma unroll
    for (int i = 0; i < 8; i++)
        #pragma unroll
        for (int j = 0; j < 8; j++) acc[i][j] = 0.f;

    for (int k0 = 0; k0 < Ed; k0 += 16) {
        #pragma unroll
        for (int i = 0; i < 2; i++) {
            float4 v = *(const float4*)&A[(size_t)(m0 + arow + 64*i) * Ed + k0 + acol];
            As[acol+0][arow+64*i] = v.x;
            As[acol+1][arow+64*i] = v.y;
            As[acol+2][arow+64*i] = v.z;
            As[acol+3][arow+64*i] = v.w;
        }
        #pragma unroll
        for (int i = 0; i < 2; i++) {
            *(float4*)&Bs[brow + 8*i][bcol] =
                *(const float4*)&W[(size_t)(k0 + brow + 8*i) * N3 + n0 + bcol];
        }
        __syncthreads();
        #pragma unroll
        for (int kk = 0; kk < 16; kk++) {
            float a[8], b[8];
            *(float4*)&a[0] = *(float4*)&As[kk][ty*8];
            *(float4*)&a[4] = *(float4*)&As[kk][ty*8+4];
            *(float4*)&b[0] = *(float4*)&Bs[kk][tx*8];
            *(float4*)&b[4] = *(float4*)&Bs[kk][tx*8+4];
            #pragma unroll
            for (int i = 0; i < 8; i++)
                #pragma unroll
                for (int j = 0; j < 8; j++)
                    acc[i][j] += a[i]*b[j];
        }
        __syncthreads();
    }

    // epilogue: column block n0+tx*8 stays inside one (which, head) 64-chunk
    const int nb    = n0 + tx*8;
    const int which = nb / Ed;
    const int hh    = (nb % Ed) >> 6;
    const int d0    = nb & 63;
    float* dst = (which == 0) ? g_Q : (which == 1) ? g_K : g_V;
    float bv[8];
    #pragma unroll
    for (int j = 0; j < 8; j++) bv[j] = bias[nb + j];
    #pragma unroll
    for (int i = 0; i < 8; i++) {
        int m = m0 + ty*8 + i;
        int bb = m >> 10, ss = m & 1023;
        float* p = &dst[(size_t)((bb*Hh + hh)*Sq + ss)*Dd + d0];
        float4 v0, v1;
        v0.x = acc[i][0]+bv[0]; v0.y = acc[i][1]+bv[1];
        v0.z = acc[i][2]+bv[2]; v0.w = acc[i][3]+bv[3];
        v1.x = acc[i][4]+bv[4]; v1.y = acc[i][5]+bv[5];
        v1.z = acc[i][6]+bv[6]; v1.w = acc[i][7]+bv[7];
        *(float4*)p     = v0;
        *(float4*)(p+4) = v1;
    }
}

// ============================================================
// GEMM 2: out = g_AO @ W_proj + b_proj.  M=8192, N=768, K=768
// ============================================================
__global__ __launch_bounds__(256) void proj_gemm(const float* __restrict__ W,
                                                 const float* __restrict__ bias,
                                                 float* __restrict__ out) {
    __shared__ float As[16][128];
    __shared__ float Bs[16][128];
    const float* A = g_AO;
    const int t  = threadIdx.x;
    const int tx = t & 15, ty = t >> 4;
    const int m0 = blockIdx.y * 128, n0 = blockIdx.x * 128;
    const int arow = t >> 2, acol = (t & 3) << 2;
    const int brow = t >> 5, bcol = (t & 31) << 2;

    float acc[8][8];
    #pragma unroll
    for (int i = 0; i < 8; i++)
        #pragma unroll
        for (int j = 0; j < 8; j++) acc[i][j] = 0.f;

    for (int k0 = 0; k0 < Ed; k0 += 16) {
        #pragma unroll
        for (int i = 0; i < 2; i++) {
            float4 v = *(const float4*)&A[(size_t)(m0 + arow + 64*i) * Ed + k0 + acol];
            As[acol+0][arow+64*i] = v.x;
            As[acol+1][arow+64*i] = v.y;
            As[acol+2][arow+64*i] = v.z;
            As[acol+3][arow+64*i] = v.w;
        }
        #pragma unroll
        for (int i = 0; i < 2; i++) {
            *(float4*)&Bs[brow + 8*i][bcol] =
                *(const float4*)&W[(size_t)(k0 + brow + 8*i) * Ed + n0 + bcol];
        }
        __syncthreads();
        #pragma unroll
        for (int kk = 0; kk < 16; kk++) {
            float a[8], b[8];
            *(float4*)&a[0] = *(float4*)&As[kk][ty*8];
            *(float4*)&a[4] = *(float4*)&As[kk][ty*8+4];
            *(float4*)&b[0] = *(float4*)&Bs[kk][tx*8];
            *(float4*)&b[4] = *(float4*)&Bs[kk][tx*8+4];
            #pragma unroll
            for (int i = 0; i < 8; i++)
                #pragma unroll
                for (int j = 0; j < 8; j++)
                    acc[i][j] += a[i]*b[j];
        }
        __syncthreads();
    }

    const int nb = n0 + tx*8;
    float bv[8];
    #pragma unroll
    for (int j = 0; j < 8; j++) bv[j] = bias[nb + j];
    #pragma unroll
    for (int i = 0; i < 8; i++) {
        int m = m0 + ty*8 + i;
        float* p = &out[(size_t)m * Ed + nb];
        float4 v0, v1;
        v0.x = acc[i][0]+bv[0]; v0.y = acc[i][1]+bv[1];
        v0.z = acc[i][2]+bv[2]; v0.w = acc[i][3]+bv[3];
        v1.x = acc[i][4]+bv[4]; v1.y = acc[i][5]+bv[5];
        v1.z = acc[i][6]+bv[6]; v1.w = acc[i][7]+bv[7];
        *(float4*)p     = v0;
        *(float4*)(p+4) = v1;
    }
}

// ============================================================
// Fused attention: scores (scaled) -> exact top-k threshold ->
// softmax -> PV.  One CTA per (b*h, 16 q-rows). 256 threads.
// ============================================================
__global__ __launch_bounds__(256) void attn_kernel() {
    extern __shared__ float sm[];
    float* q_s  = sm;                       // QT*Dd      = 1024
    float* sc   = sm + QT*Dd;               // QT*Sq      = 16384
    float* kv   = sc + QT*Sq;               // KT*KVP     = 4352
    float* invs = kv + KT*KVP;              // QT

    const int t  = threadIdx.x;
    const int bh = blockIdx.y;
    const int q0 = blockIdx.x * QT;
    const float* Qg = g_Q + (size_t)bh*Sq*Dd;
    const float* Kg = g_K + (size_t)bh*Sq*Dd;
    const float* Vg = g_V + (size_t)bh*Sq*Dd;

    // stage q tile (pre-scaled by head_dim^-0.5 = 0.125)
    {
        int r = t >> 4, c = (t & 15) << 2;
        float4 v = *(const float4*)&Qg[(size_t)(q0 + r)*Dd + c];
        v.x *= 0.125f; v.y *= 0.125f; v.z *= 0.125f; v.w *= 0.125f;
        *(float4*)&q_s[r*Dd + c] = v;
    }

    const int jt = t & 63;   // key within tile
    const int gq = t >> 6;   // q-group: handles rows gq, gq+4, gq+8, gq+12

    // ---- scores: sc[q][k] = (q_row . k_row) ----
    for (int kt0 = 0; kt0 < Sq; kt0 += KT) {
        __syncthreads();
        #pragma unroll
        for (int i = 0; i < 4; i++) {
            int r = (t >> 4) + 16*i, c = (t & 15) << 2;
            *(float4*)&kv[r*KVP + c] = *(const float4*)&Kg[(size_t)(kt0 + r)*Dd + c];
        }
        __syncthreads();
        float a0 = 0.f, a1 = 0.f, a2 = 0.f, a3 = 0.f;
        #pragma unroll
        for (int c = 0; c < Dd; c += 4) {
            float4 k4 = *(float4*)&kv[jt*KVP + c];
            float4 x;
            x = *(float4*)&q_s[(gq+ 0)*Dd + c]; a0 += x.x*k4.x + x.y*k4.y + x.z*k4.z + x.w*k4.w;
            x = *(float4*)&q_s[(gq+ 4)*Dd + c]; a1 += x.x*k4.x + x.y*k4.y + x.z*k4.z + x.w*k4.w;
            x = *(float4*)&q_s[(gq+ 8)*Dd + c]; a2 += x.x*k4.x + x.y*k4.y + x.z*k4.z + x.w*k4.w;
            x = *(float4*)&q_s[(gq+12)*Dd + c]; a3 += x.x*k4.x + x.y*k4.y + x.z*k4.z + x.w*k4.w;
        }
        sc[(gq+ 0)*Sq + kt0 + jt] = a0;
        sc[(gq+ 4)*Sq + kt0 + jt] = a1;
        sc[(gq+ 8)*Sq + kt0 + jt] = a2;
        sc[(gq+12)*Sq + kt0 + jt] = a3;
    }
    __syncthreads();

    // ---- exact top-k threshold (kth largest) + softmax in place ----
    // warp w handles rows 2w and 2w+1; keys cached in 32 regs/lane.
    {
        const int warp = t >> 5, lane = t & 31;
        for (int r = warp*2; r < warp*2 + 2; r++) {
            float* row = sc + r*Sq;
            unsigned u[32];
            float mx = -3.4e38f;
            #pragma unroll
            for (int i = 0; i < 32; i++) {
                float f = row[i*32 + lane];
                mx = fmaxf(mx, f);
                unsigned b = __float_as_uint(f);
                u[i] = b ^ (unsigned)(((int)b >> 31) | (int)0x80000000);
            }
            #pragma unroll
            for (int o = 16; o; o >>= 1) mx = fmaxf(mx, __shfl_xor_sync(0xffffffffu, mx, o));

            // kth-largest = max x with count(u >= x) >= TOPK; bitwise binary search
            unsigned pref = 0;
            #pragma unroll 1
            for (int bb = 31; bb >= 0; bb--) {
                unsigned trial = pref | (1u << bb);
                int c = 0;
                #pragma unroll
                for (int i = 0; i < 32; i++) c += (u[i] >= trial) ? 1 : 0;
                c = (int)__reduce_add_sync(0xffffffffu, (unsigned)c);
                if (c >= TOPK) pref = trial;
            }

            float ssum = 0.f;
            #pragma unroll
            for (int i = 0; i < 32; i++) {
                float p = 0.f;
                if (u[i] >= pref) {
                    unsigned b = (u[i] & 0x80000000u) ? (u[i] ^ 0x80000000u) : ~u[i];
                    p = __expf(__uint_as_float(b) - mx);
                }
                ssum += p;
                row[i*32 + lane] = p;
            }
            #pragma unroll
            for (int o = 16; o; o >>= 1) ssum += __shfl_xor_sync(0xffffffffu, ssum, o);
            if (lane == 0) invs[r] = 1.f / ssum;
        }
    }

    // ---- PV: out[q][d] = sum_k p[q][k] * V[k][d] ----
    const int dd = t & 63;   // thread owns column dd, rows gq+4i
    float o0 = 0.f, o1 = 0.f, o2 = 0.f, o3 = 0.f;
    for (int kt0 = 0; kt0 < Sq; kt0 += KT) {
        __syncthreads();
        #pragma unroll
        for (int i = 0; i < 4; i++) {
            int r = (t >> 4) + 16*i, c = (t & 15) << 2;
            *(float4*)&kv[r*KVP + c] = *(const float4*)&Vg[(size_t)(kt0 + r)*Dd + c];
        }
        __syncthreads();
        #pragma unroll
        for (int j = 0; j < KT; j += 4) {
            float v0 = kv[(j+0)*KVP + dd];
            float v1 = kv[(j+1)*KVP + dd];
            float v2 = kv[(j+2)*KVP + dd];
            float v3 = kv[(j+3)*KVP + dd];
            float4 p;
            p = *(float4*)&sc[(gq+ 0)*Sq + kt0 + j]; o0 += p.x*v0 + p.y*v1 + p.z*v2 + p.w*v3;
            p = *(float4*)&sc[(gq+ 4)*Sq + kt0 + j]; o1 += p.x*v0 + p.y*v1 + p.z*v2 + p.w*v3;
            p = *(float4*)&sc[(gq+ 8)*Sq + kt0 + j]; o2 += p.x*v0 + p.y*v1 + p.z*v2 + p.w*v3;
            p = *(float4*)&sc[(gq+12)*Sq + kt0 + j]; o3 += p.x*v0 + p.y*v1 + p.z*v2 + p.w*v3;
        }
    }

    const int bb = bh / Hh, hh = bh % Hh;
    #pragma unroll
    for (int i = 0; i < 4; i++) {
        int q  = gq + 4*i;
        float v = (i == 0) ? o0 : (i == 1) ? o1 : (i == 2) ? o2 : o3;
        v *= invs[q];
        int s_ = q0 + q;
        g_AO[(size_t)((bb*Sq + s_)*Hh + hh)*Dd + dd] = v;
    }
}

// ============================================================
// launch
// ============================================================
extern "C" void kernel_launch(void* const* d_in, const int* in_sizes, int n_in,
                              void* d_out, int out_size) {
    const float* hidden = (const float*)d_in[0];
    const float* Wqkv   = (const float*)d_in[1];
    const float* bqkv   = (const float*)d_in[2];
    const float* Wproj  = (const float*)d_in[3];
    const float* bproj  = (const float*)d_in[4];
    float* out = (float*)d_out;

    const int attn_smem = (QT*Dd + QT*Sq + KT*KVP + QT) * (int)sizeof(float); // 87104 B
    cudaFuncSetAttribute(attn_kernel, cudaFuncAttributeMaxDynamicSharedMemorySize, attn_smem);

    qkv_gemm<<<dim3(N3/128, (Bz*Sq)/128), 256>>>(hidden, Wqkv, bqkv);
    attn_kernel<<<dim3(Sq/QT, Bz*Hh), 256, attn_smem>>>();
    proj_gemm<<<dim3(Ed/128, (Bz*Sq)/128), 256>>>(Wproj, bproj, out);
}